// round 7
// baseline (speedup 1.0000x reference)
#include <cuda_runtime.h>
#include <cstdint>

// ============================================================================
// LSTM_34883724378521 : T=60, C=H=128, N=4096, TOUT=114
// Persistent cluster kernel. grid = (8 gate tiles x 32 batch tiles); each
// 8-CTA cluster owns one batch tile for all 114 steps (HW cluster barrier
// between steps). Weights resident in smem (chunk-major), c-state in regs.
// CTA tile M=128 x N=64, 256 threads, 2 CTAs/SM.
// A-pipeline: 2 buffers, prefetch distance 1 (race-free).
// ============================================================================
#define NB 4096
#define HD 128
#define NG 512

__device__ __forceinline__ uint32_t smem_u32(const void* p) {
    uint32_t a;
    asm("{ .reg .u64 t; cvta.to.shared.u64 t, %1; cvt.u32.u64 %0, t; }"
        : "=r"(a) : "l"(p));
    return a;
}
__device__ __forceinline__ void cp16(uint32_t dst, const void* src) {
    asm volatile("cp.async.cg.shared.global [%0], [%1], 16;" :: "r"(dst), "l"(src));
}
#define CP_COMMIT() asm volatile("cp.async.commit_group;" ::: "memory")
#define CP_WAIT(n)  asm volatile("cp.async.wait_group %0;" :: "n"(n) : "memory")
#define CLUSTER_ARRIVE() asm volatile("barrier.cluster.arrive.aligned;" ::: "memory")
#define CLUSTER_WAIT()   asm volatile("barrier.cluster.wait.aligned;" ::: "memory")

__device__ __forceinline__ uint32_t rna_tf32(float v) {
    uint32_t u; asm("cvt.rna.tf32.f32 %0, %1;" : "=r"(u) : "f"(v)); return u;
}
__device__ __forceinline__ void mma8(float* d, const uint32_t* a, const uint32_t* b) {
    asm volatile(
        "mma.sync.aligned.m16n8k8.row.col.f32.tf32.tf32.f32 "
        "{%0,%1,%2,%3}, {%4,%5,%6,%7}, {%8,%9}, {%0,%1,%2,%3};"
        : "+f"(d[0]), "+f"(d[1]), "+f"(d[2]), "+f"(d[3])
        : "r"(a[0]), "r"(a[1]), "r"(a[2]), "r"(a[3]), "r"(b[0]), "r"(b[1]));
}
__device__ __forceinline__ float sigf(float x)   { return 1.0f / (1.0f + __expf(-x)); }
__device__ __forceinline__ float tanhf_(float x) { return 1.0f - 2.0f / (__expf(2.0f * x) + 1.0f); }

// ---------------------------------------------------------------------------
// persistent device state
// ---------------------------------------------------------------------------
__device__ float g_Hbuf0[HD * NB];   // h state, h-major [H][N] (tf32-rounded)
__device__ float g_Hbuf1[HD * NB];
__device__ float g_W1[NG * 256];     // permuted [4h+g][x|h], tf32-rounded
__device__ float g_W2[NG * 128];     // permuted (W_ih+W_hh), tf32-rounded
__device__ float g_bias[NG];         // permuted b_ih + b_hh

// ---------------------------------------------------------------------------
// prep: row perm r = 4*h+g <- g*128+h ; RNA-round weights; zero h state
// (identical to the round-5 proven version)
// ---------------------------------------------------------------------------
__global__ void prep_kernel(const float* __restrict__ Wih, const float* __restrict__ Whh,
                            const float* __restrict__ bih, const float* __restrict__ bhh) {
    int tid = blockIdx.x * 256 + threadIdx.x;       // 512*256 = 131072
    int r = tid >> 8, k = tid & 255;
    int h = r >> 2, g = r & 3;
    int orig = g * HD + h;
    float v = (k < 128) ? Wih[orig * HD + k] : Whh[orig * HD + (k - 128)];
    g_W1[r * 256 + k] = __uint_as_float(rna_tf32(v));
    if (k < 128)
        g_W2[r * 128 + k] =
            __uint_as_float(rna_tf32(Wih[orig * HD + k] + Whh[orig * HD + k]));
    if (k == 0) g_bias[r] = bih[orig] + bhh[orig];
    for (int i = tid; i < HD * NB; i += 131072) g_Hbuf0[i] = 0.0f;
}

// ---------------------------------------------------------------------------
// smem layout (float offsets):
//   bias(64) | W: 8 chunks x (64 rows x 36 stride) | A: 2 x (32 x 136)
// H2 stage (16 x 130) aliases A buffer 0 after the mainloop.
// ---------------------------------------------------------------------------
static constexpr int A_STR = 136, B_STR = 36, H_STR = 130;
static constexpr int A_FL  = 32 * A_STR;               // 4352
static constexpr int WCH   = 64 * B_STR;               // 2304 floats per chunk
static constexpr int OFF_BIAS = 0;
static constexpr int OFF_W    = 64;
static constexpr int OFF_A    = OFF_W + 8 * WCH;       // 18496
static constexpr int SM_FLOATS = OFF_A + 2 * A_FL;     // 27200
static constexpr int SM_BYTES  = SM_FLOATS * 4;        // 108800 -> 2 CTAs/SM

__global__ void __launch_bounds__(256, 2) __cluster_dims__(8, 1, 1)
lstm_persist(const float* __restrict__ img, float* __restrict__ out, int T, int TOUT) {
    extern __shared__ float smf[];
    const uint32_t sb = smem_u32(smf);
    const int tid = threadIdx.x, lane = tid & 31, wid = tid >> 5;
    const int gq = lane >> 2, tig = lane & 3;
    const int wm = wid >> 1, wn = wid & 1;             // 4 x 2 warp grid
    const int j = blockIdx.x, n0 = blockIdx.y * 128;   // j: 64 gate cols

    if (tid < 64) smf[OFF_BIAS + tid] = g_bias[j * 64 + tid];

    // scatter resident weights into chunk-major smem: chunk = k/32,
    // within chunk: row-major 64 x 32 with stride 36 (round-5 proven layout)
    auto loadW1 = [&]() {
        for (int i = tid; i < 64 * 64; i += 256) {      // 64 rows x 64 granules
            int row = i >> 6, g16 = i & 63;
            cp16(sb + (uint32_t)(OFF_W + (g16 >> 3) * WCH + row * B_STR +
                                 ((g16 & 7) << 2)) * 4,
                 g_W1 + (size_t)(j * 64 + row) * 256 + (g16 << 2));
        }
        CP_COMMIT();
    };
    auto loadW2 = [&]() {
        for (int i = tid; i < 64 * 32; i += 256) {      // 64 rows x 32 granules
            int row = i >> 5, g16 = i & 31;
            cp16(sb + (uint32_t)(OFF_W + (g16 >> 3) * WCH + row * B_STR +
                                 ((g16 & 7) << 2)) * 4,
                 g_W2 + (size_t)(j * 64 + row) * 128 + (g16 << 2));
        }
        CP_COMMIT();
    };
    loadW1();

    float c[8];
    #pragma unroll
    for (int i = 0; i < 8; i++) c[i] = 0.0f;

    CP_WAIT(0);
    __syncthreads();

    for (int t = 0; t < TOUT; t++) {
        const float* hprev = (t & 1) ? g_Hbuf1 : g_Hbuf0;
        float*       hnext = (t & 1) ? g_Hbuf0 : g_Hbuf1;
        const bool p1 = (t < T);
        const float* xs = img + (size_t)t * HD * NB;
        const int nch = p1 ? 8 : 4;

        if (t == T) loadW2();              // swap to pre-summed phase-2 weights
                                           // (first CP_WAIT below covers it)

        auto loadC = [&](int ch) {         // A: 32 k-rows x 128 m
            const int buf = ch & 1;
            const float* asrc = (p1 && ch < 4) ? xs : hprev;
            const int kr = (p1 && ch >= 4) ? (ch - 4) * 32 : ch * 32;
            const uint32_t ab = sb + (uint32_t)(OFF_A + buf * A_FL) * 4;
            #pragma unroll
            for (int it = 0; it < 4; it++) {
                int idx = tid + it * 256;
                int kk = idx >> 5, mp = (idx & 31) << 2;
                cp16(ab + (uint32_t)(kk * A_STR + mp) * 4,
                     asrc + (size_t)(kr + kk) * NB + n0 + mp);
            }
            CP_COMMIT();
        };

        float acc[2][4][4];
        #pragma unroll
        for (int a0 = 0; a0 < 2; a0++)
            #pragma unroll
            for (int a1 = 0; a1 < 4; a1++)
                #pragma unroll
                for (int a2 = 0; a2 < 4; a2++) acc[a0][a1][a2] = 0.0f;

        loadC(0);
        for (int ch = 0; ch < nch; ch++) {
            CP_WAIT(0);                    // chunk ch (+W swap at t==T) landed
            __syncthreads();               // and mma(ch-1) done by all warps
            if (ch + 1 < nch) loadC(ch + 1);   // writes buf (ch+1)&1 — free
            const float* As = smf + OFF_A + (ch & 1) * A_FL;
            const float* Bs = smf + OFF_W + ch * WCH;
            const bool docvt = (p1 && ch < 4);

            #pragma unroll
            for (int kc = 0; kc < 4; kc++) {
                const int k0 = kc * 8;
                uint32_t a[2][4];
                #pragma unroll
                for (int mt = 0; mt < 2; mt++) {
                    const int r0 = wm * 32 + mt * 16 + gq;
                    float v0 = As[(k0 + tig) * A_STR + r0];
                    float v1 = As[(k0 + tig) * A_STR + r0 + 8];
                    float v2 = As[(k0 + tig + 4) * A_STR + r0];
                    float v3 = As[(k0 + tig + 4) * A_STR + r0 + 8];
                    if (docvt) {
                        a[mt][0] = rna_tf32(v0); a[mt][1] = rna_tf32(v1);
                        a[mt][2] = rna_tf32(v2); a[mt][3] = rna_tf32(v3);
                    } else {
                        a[mt][0] = __float_as_uint(v0); a[mt][1] = __float_as_uint(v1);
                        a[mt][2] = __float_as_uint(v2); a[mt][3] = __float_as_uint(v3);
                    }
                }
                #pragma unroll
                for (int nt = 0; nt < 4; nt++) {
                    const int c0 = wn * 32 + nt * 8 + gq;
                    uint32_t b[2];
                    b[0] = __float_as_uint(Bs[c0 * B_STR + k0 + tig]);
                    b[1] = __float_as_uint(Bs[c0 * B_STR + k0 + tig + 4]);
                    mma8(acc[0][nt], a[0], b);
                    mma8(acc[1][nt], a[1], b);
                }
            }
        }
        __syncthreads();         // mma done -> A buf 0 reusable as H2 stage

        // ---- shuffle epilogue: pair (i,f) with (g,o) via lane^1; c in regs --
        float* H2 = smf + OFF_A;             // 16 units x H_STR
        const int mymt = tig & 1;
        const int r0e = wm * 32 + mymt * 16 + gq;
        #pragma unroll
        for (int nt = 0; nt < 4; nt++) {
            const int u = wn * 8 + nt * 2 + (tig >> 1);
            float oth[4];
            #pragma unroll
            for (int e = 0; e < 4; e++)
                oth[e] = __shfl_xor_sync(0xffffffffu, acc[mymt ^ 1][nt][e], 1);
            const float b0 = smf[OFF_BIAS + 4 * u + 0];
            const float b1 = smf[OFF_BIAS + 4 * u + 1];
            const float b2 = smf[OFF_BIAS + 4 * u + 2];
            const float b3 = smf[OFF_BIAS + 4 * u + 3];
            #pragma unroll
            for (int e2 = 0; e2 < 2; e2++) {
                const float ow0 = acc[mymt][nt][2 * e2], ow1 = acc[mymt][nt][2 * e2 + 1];
                const float ot0 = oth[2 * e2],           ot1 = oth[2 * e2 + 1];
                float gi, gf, gg, go;
                if (mymt == 0) { gi = ow0; gf = ow1; gg = ot0; go = ot1; }
                else           { gg = ow0; go = ow1; gi = ot0; gf = ot1; }
                gi += b0; gf += b1; gg += b2; go += b3;
                const int row = r0e + 8 * e2;
                const int ci = nt * 2 + e2;
                const float cn = sigf(gf) * c[ci] + sigf(gi) * tanhf_(gg);
                c[ci] = cn;
                H2[u * H_STR + row] = sigf(go) * tanhf_(cn);
            }
        }
        __syncthreads();

        // ---- h-state writeback (h-major, pre-rounded to tf32) ----
        #pragma unroll
        for (int q = 0; q < 2; q++) {
            const int u = wid * 2 + q;
            #pragma unroll
            for (int mk = 0; mk < 4; mk++) {
                const int m = mk * 32 + lane;
                hnext[(size_t)(j * 16 + u) * NB + n0 + m] =
                    __uint_as_float(rna_tf32(H2[u * H_STR + m]));
            }
        }
        // ---- output: out[n][t][h], 64B contiguous (16 h per CTA) ----
        const int hh = lane & 15, rp = lane >> 4;
        #pragma unroll
        for (int i2 = 0; i2 < 8; i2++) {
            const int mr = wid * 16 + i2 * 2 + rp;
            out[(size_t)(n0 + mr) * TOUT * HD + (size_t)t * HD + j * 16 + hh] =
                H2[hh * H_STR + mr];
        }

        // ---- cluster barrier: h of all 8 gate CTAs visible for next step ----
        if (t + 1 < TOUT) {
            CLUSTER_ARRIVE();
            CLUSTER_WAIT();
        }
    }
}

// ---------------------------------------------------------------------------
// launch: prep + one persistent cluster kernel
// ---------------------------------------------------------------------------
extern "C" void kernel_launch(void* const* d_in, const int* in_sizes, int n_in,
                              void* d_out, int out_size) {
    const float* img = (const float*)d_in[0];
    const float* Wih = (const float*)d_in[2];
    const float* Whh = (const float*)d_in[3];
    const float* bih = (const float*)d_in[4];
    const float* bhh = (const float*)d_in[5];
    float* out = (float*)d_out;

    const int T    = in_sizes[0] / (HD * NB);       // 60
    const int TOUT = out_size / (NB * HD);          // 114

    cudaFuncSetAttribute((const void*)lstm_persist,
                         cudaFuncAttributeMaxDynamicSharedMemorySize, SM_BYTES);

    prep_kernel<<<512, 256>>>(Wih, Whh, bih, bhh);

    dim3 grid(8, NB / 128);                         // 32 clusters of 8 CTAs
    lstm_persist<<<grid, 256, SM_BYTES>>>(img, out, T, TOUT);
}

// round 8
// speedup vs baseline: 2.3754x; 2.3754x over previous
#include <cuda_runtime.h>
#include <cstdint>

// ============================================================================
// LSTM_34883724378521 : T=60, C=H=128, N=4096, TOUT=114
// tf32 mma.sync, 1 kernel/step. CTA tile M=64 x N=64, 128 threads (4 warps),
// grid = (8 gate tiles x 64 batch tiles) = 512 CTAs -> 4 CTAs/SM.
// 3-buffer cp.async pipeline (prefetch dist 2), pair-interleaved B for LDS.64.
// ============================================================================
#define NB 4096
#define HD 128
#define NG 512

__device__ __forceinline__ uint32_t smem_u32(const void* p) {
    uint32_t a;
    asm("{ .reg .u64 t; cvta.to.shared.u64 t, %1; cvt.u32.u64 %0, t; }"
        : "=r"(a) : "l"(p));
    return a;
}
__device__ __forceinline__ void cp16(uint32_t dst, const void* src) {
    asm volatile("cp.async.cg.shared.global [%0], [%1], 16;" :: "r"(dst), "l"(src));
}
#define CP_COMMIT() asm volatile("cp.async.commit_group;" ::: "memory")
#define CP_WAIT(n)  asm volatile("cp.async.wait_group %0;" :: "n"(n) : "memory")

__device__ __forceinline__ uint32_t rna_tf32(float v) {
    uint32_t u; asm("cvt.rna.tf32.f32 %0, %1;" : "=r"(u) : "f"(v)); return u;
}
__device__ __forceinline__ void mma8(float* d, const uint32_t* a, const uint32_t* b) {
    asm volatile(
        "mma.sync.aligned.m16n8k8.row.col.f32.tf32.tf32.f32 "
        "{%0,%1,%2,%3}, {%4,%5,%6,%7}, {%8,%9}, {%0,%1,%2,%3};"
        : "+f"(d[0]), "+f"(d[1]), "+f"(d[2]), "+f"(d[3])
        : "r"(a[0]), "r"(a[1]), "r"(a[2]), "r"(a[3]), "r"(b[0]), "r"(b[1]));
}
__device__ __forceinline__ float sigf(float x)   { return 1.0f / (1.0f + __expf(-x)); }
__device__ __forceinline__ float tanhf_(float x) { return 1.0f - 2.0f / (__expf(2.0f * x) + 1.0f); }

// ---------------------------------------------------------------------------
// persistent device state
// ---------------------------------------------------------------------------
__device__ float g_Hbuf0[HD * NB];   // h state, h-major [H][N] (tf32-rounded)
__device__ float g_Hbuf1[HD * NB];
__device__ float g_Cbuf [HD * NB];   // c state, h-major
__device__ float g_W1[NG * 256];     // permuted rows, k pair-interleaved
__device__ float g_W2[NG * 128];     // (W_ih+W_hh), same k interleave
__device__ float g_bias[NG];         // permuted b_ih + b_hh

// ---------------------------------------------------------------------------
// prep: row perm r = 4*h+g <- g*128+h ;
// k pair-interleave within 8-blocks: scol = (k&~7) + ((k&3)<<1) + ((k&7)>>2)
// so fragment pair (k, k+4) lands adjacent -> B loads become LDS.64.
// RNA-round weights; zero state.
// ---------------------------------------------------------------------------
__global__ void prep_kernel(const float* __restrict__ Wih, const float* __restrict__ Whh,
                            const float* __restrict__ bih, const float* __restrict__ bhh) {
    int tid = blockIdx.x * 256 + threadIdx.x;       // 512*256 = 131072
    int r = tid >> 8, k = tid & 255;
    int h = r >> 2, g = r & 3;
    int orig = g * HD + h;
    int q = k & 7;
    int scol = (k & ~7) + ((q & 3) << 1) + (q >> 2);
    float v = (k < 128) ? Wih[orig * HD + k] : Whh[orig * HD + (k - 128)];
    g_W1[r * 256 + scol] = __uint_as_float(rna_tf32(v));
    if (k < 128)
        g_W2[r * 128 + scol] =
            __uint_as_float(rna_tf32(Wih[orig * HD + k] + Whh[orig * HD + k]));
    if (k == 0) g_bias[r] = bih[orig] + bhh[orig];
    for (int i = tid; i < HD * NB; i += 131072) {
        g_Hbuf0[i] = 0.0f;
        g_Cbuf[i]  = 0.0f;
    }
}

// ---------------------------------------------------------------------------
// smem layout (float offsets): bias(64) | 3x A(32x72) | 3x B(64x36)
// H2 stage (16 x 66) aliases A buffer 0 after the mainloop.
// ---------------------------------------------------------------------------
static constexpr int A_STR = 72, B_STR = 36, H_STR = 66;
static constexpr int A_FL  = 32 * A_STR;      // 2304
static constexpr int B_FL  = 64 * B_STR;      // 2304
static constexpr int OFF_BIAS = 0;
static constexpr int OFF_A    = 64;
static constexpr int OFF_B    = OFF_A + 3 * A_FL;
static constexpr int SM_FLOATS = OFF_B + 3 * B_FL;  // 13888
static constexpr int SM_BYTES  = SM_FLOATS * 4;     // 55552 -> 4 CTAs/SM

// ---------------------------------------------------------------------------
// fused step. CTA tile M=64 x N=64 (16 hidden units), K = NCH*32.
// 4 warps: 2 wm x 2 wn, warp tile M=32 x N=32.
// ---------------------------------------------------------------------------
template <int NCH>
__global__ void __launch_bounds__(128, 4)
lstm_step(const float* __restrict__ xsrc,   // [128][NB] x_t slice or null
          const float* __restrict__ hprev,  // [128][NB] (pre-rounded tf32)
          float* __restrict__ hnext,
          float* __restrict__ out, int t_out, int TOUT) {
    extern __shared__ float smf[];
    const uint32_t sb = smem_u32(smf);
    const int tid = threadIdx.x, lane = tid & 31, wid = tid >> 5;
    const int gq = lane >> 2, tig = lane & 3;
    const int wm = wid >> 1, wn = wid & 1;            // 2 x 2 warp grid
    const int j = blockIdx.x, n0 = blockIdx.y * 64;   // j: 64 gate cols

    if (tid < 64) smf[OFF_BIAS + tid] = g_bias[j * 64 + tid];

    const float* W = (NCH == 8) ? g_W1 : g_W2;
    const int KT = NCH * 32;

    auto loadC = [&](int ch) {
        const int buf = ch % 3;
        const float* asrc = (NCH == 8 && ch < 4) ? xsrc : hprev;
        const int kr = (NCH == 8 && ch >= 4) ? (ch - 4) * 32 : ch * 32;
        const uint32_t ab = sb + (uint32_t)(OFF_A + buf * A_FL) * 4;
        const uint32_t bb = sb + (uint32_t)(OFF_B + buf * B_FL) * 4;
        #pragma unroll
        for (int it = 0; it < 4; it++) {   // A: 32 k-rows x 64 m
            int idx = tid + it * 128;
            int kk = idx >> 4, mp = (idx & 15) << 2;
            cp16(ab + (uint32_t)(kk * A_STR + mp) * 4,
                 asrc + (size_t)(kr + kk) * NB + n0 + mp);
        }
        #pragma unroll
        for (int it = 0; it < 4; it++) {   // B: 64 gate-cols x 32 k
            int idx = tid + it * 128;
            int n = idx >> 3, q = (idx & 7) << 2;
            cp16(bb + (uint32_t)(n * B_STR + q) * 4,
                 W + (size_t)(j * 64 + n) * KT + ch * 32 + q);
        }
        CP_COMMIT();
    };

    float acc[2][4][4];
    #pragma unroll
    for (int a0 = 0; a0 < 2; a0++)
        #pragma unroll
        for (int a1 = 0; a1 < 4; a1++)
            #pragma unroll
            for (int a2 = 0; a2 < 4; a2++) acc[a0][a1][a2] = 0.0f;

    loadC(0);
    loadC(1);
    #pragma unroll
    for (int ch = 0; ch < NCH; ch++) {
        if (ch == NCH - 1) { CP_WAIT(0); } else { CP_WAIT(1); }
        __syncthreads();                       // chunk ch ready; mma(ch-1) done
        if (ch + 2 < NCH) loadC(ch + 2);
        const float* As = smf + OFF_A + (ch % 3) * A_FL;
        const float* Bs = smf + OFF_B + (ch % 3) * B_FL;
        const bool docvt = (NCH == 8 && ch < 4);

        #pragma unroll
        for (int kc = 0; kc < 4; kc++) {
            const int k0 = kc * 8;
            uint32_t a[2][4];
            #pragma unroll
            for (int mt = 0; mt < 2; mt++) {
                const int r0 = wm * 32 + mt * 16 + gq;
                // A k-index also pair-interleaved? NO: A uses natural k order.
                // (interleave applies to W columns only; A rows are k-natural,
                //  so index A with natural k: rows k0+tig and k0+tig+4.)
                float v0 = As[(k0 + tig) * A_STR + r0];
                float v1 = As[(k0 + tig) * A_STR + r0 + 8];
                float v2 = As[(k0 + tig + 4) * A_STR + r0];
                float v3 = As[(k0 + tig + 4) * A_STR + r0 + 8];
                if (docvt) {
                    a[mt][0] = rna_tf32(v0); a[mt][1] = rna_tf32(v1);
                    a[mt][2] = rna_tf32(v2); a[mt][3] = rna_tf32(v3);
                } else {
                    a[mt][0] = __float_as_uint(v0); a[mt][1] = __float_as_uint(v1);
                    a[mt][2] = __float_as_uint(v2); a[mt][3] = __float_as_uint(v3);
                }
            }
            #pragma unroll
            for (int nt = 0; nt < 4; nt++) {
                const int c0 = wn * 32 + nt * 8 + gq;
                // pair-interleaved W: (k0+tig, k0+tig+4) adjacent -> LDS.64
                const uint2 bp = *(const uint2*)(Bs + c0 * B_STR + k0 + 2 * tig);
                uint32_t b[2] = {bp.x, bp.y};
                mma8(acc[0][nt], a[0], b);
                mma8(acc[1][nt], a[1], b);
            }
        }
    }
    __syncthreads();     // all mma done -> A bufs reusable as H2 stage

    // ---- shuffle epilogue: pair (i,f) with (g,o) via lane^1 ----
    float* H2 = smf + OFF_A;            // 16 units x H_STR (64 m rows)
    const int mymt = tig & 1;
    const int r0e = wm * 32 + mymt * 16 + gq;
    #pragma unroll
    for (int nt = 0; nt < 4; nt++) {
        const int u = wn * 8 + nt * 2 + (tig >> 1);
        float oth[4];
        #pragma unroll
        for (int e = 0; e < 4; e++)
            oth[e] = __shfl_xor_sync(0xffffffffu, acc[mymt ^ 1][nt][e], 1);
        const float b0 = smf[OFF_BIAS + 4 * u + 0];
        const float b1 = smf[OFF_BIAS + 4 * u + 1];
        const float b2 = smf[OFF_BIAS + 4 * u + 2];
        const float b3 = smf[OFF_BIAS + 4 * u + 3];
        #pragma unroll
        for (int e2 = 0; e2 < 2; e2++) {
            const float ow0 = acc[mymt][nt][2 * e2], ow1 = acc[mymt][nt][2 * e2 + 1];
            const float ot0 = oth[2 * e2],           ot1 = oth[2 * e2 + 1];
            float gi, gf, gg, go;
            if (mymt == 0) { gi = ow0; gf = ow1; gg = ot0; go = ot1; }
            else           { gg = ow0; go = ow1; gi = ot0; gf = ot1; }
            gi += b0; gf += b1; gg += b2; go += b3;
            const int row = r0e + 8 * e2;
            const size_t ci = (size_t)(j * 16 + u) * NB + n0 + row;
            const float cold = g_Cbuf[ci];
            const float cn = sigf(gf) * cold + sigf(gi) * tanhf_(gg);
            g_Cbuf[ci] = cn;
            H2[u * H_STR + row] = sigf(go) * tanhf_(cn);
        }
    }
    __syncthreads();

    // ---- h-state writeback (h-major, pre-rounded to tf32) ----
    #pragma unroll
    for (int q = 0; q < 4; q++) {
        const int u = wid * 4 + q;
        #pragma unroll
        for (int mk = 0; mk < 2; mk++) {
            const int m = mk * 32 + lane;
            hnext[(size_t)(j * 16 + u) * NB + n0 + m] =
                __uint_as_float(rna_tf32(H2[u * H_STR + m]));
        }
    }
    // ---- output: out[n][t][h], 64B contiguous (16 h per CTA) ----
    const int hh = lane & 15, rp = lane >> 4;
    #pragma unroll
    for (int i2 = 0; i2 < 8; i2++) {
        const int mr = wid * 16 + i2 * 2 + rp;
        out[(size_t)(n0 + mr) * TOUT * HD + (size_t)t_out * HD + j * 16 + hh] =
            H2[hh * H_STR + mr];
    }
}

// ---------------------------------------------------------------------------
// launch: prep + 60 K=256 steps + 54 K=128 steps
// ---------------------------------------------------------------------------
extern "C" void kernel_launch(void* const* d_in, const int* in_sizes, int n_in,
                              void* d_out, int out_size) {
    const float* img = (const float*)d_in[0];
    const float* Wih = (const float*)d_in[2];
    const float* Whh = (const float*)d_in[3];
    const float* bih = (const float*)d_in[4];
    const float* bhh = (const float*)d_in[5];
    float* out = (float*)d_out;

    const int T    = in_sizes[0] / (HD * NB);       // 60
    const int TOUT = out_size / (NB * HD);          // 114

    void *h0p, *h1p;
    cudaGetSymbolAddress(&h0p, g_Hbuf0);
    cudaGetSymbolAddress(&h1p, g_Hbuf1);
    float* hb[2] = {(float*)h0p, (float*)h1p};

    cudaFuncSetAttribute((const void*)lstm_step<8>,
                         cudaFuncAttributeMaxDynamicSharedMemorySize, SM_BYTES);
    cudaFuncSetAttribute((const void*)lstm_step<4>,
                         cudaFuncAttributeMaxDynamicSharedMemorySize, SM_BYTES);

    prep_kernel<<<512, 256>>>(Wih, Whh, bih, bhh);

    dim3 grid(8, NB / 64);                          // 512 CTAs, 4/SM
    for (int t = 0; t < TOUT; t++) {
        float* hp = hb[t & 1];
        float* hn = hb[(t + 1) & 1];
        if (t < T) {
            lstm_step<8><<<grid, 128, SM_BYTES>>>(
                img + (size_t)t * HD * NB, hp, hn, out, t, TOUT);
        } else {
            lstm_step<4><<<grid, 128, SM_BYTES>>>(
                nullptr, hp, hn, out, t, TOUT);
        }
    }
}

// round 9
// speedup vs baseline: 2.6307x; 1.1075x over previous
#include <cuda_runtime.h>
#include <cstdint>

// ============================================================================
// LSTM_34883724378521 : T=60, C=H=128, N=4096, TOUT=114
// tf32 mma.sync, 1 kernel/step. grid = (8 gate tiles x 32 batch tiles) = 256
// CTAs -> 2 CTAs/SM. CTA tile M=128 x N=64.
// Phase-1 chunk order: h chunks first (L2-warm), img chunks last (DRAM),
// 4-buffer cp.async pipeline with prefetch distance 3 to hide DRAM latency.
// ============================================================================
#define NB 4096
#define HD 128
#define NG 512

__device__ __forceinline__ uint32_t smem_u32(const void* p) {
    uint32_t a;
    asm("{ .reg .u64 t; cvta.to.shared.u64 t, %1; cvt.u32.u64 %0, t; }"
        : "=r"(a) : "l"(p));
    return a;
}
__device__ __forceinline__ void cp16(uint32_t dst, const void* src) {
    asm volatile("cp.async.cg.shared.global [%0], [%1], 16;" :: "r"(dst), "l"(src));
}
#define CP_COMMIT() asm volatile("cp.async.commit_group;" ::: "memory")
#define CP_WAIT(n)  asm volatile("cp.async.wait_group %0;" :: "n"(n) : "memory")

__device__ __forceinline__ uint32_t rna_tf32(float v) {
    uint32_t u; asm("cvt.rna.tf32.f32 %0, %1;" : "=r"(u) : "f"(v)); return u;
}
__device__ __forceinline__ void mma8(float* d, const uint32_t* a, const uint32_t* b) {
    asm volatile(
        "mma.sync.aligned.m16n8k8.row.col.f32.tf32.tf32.f32 "
        "{%0,%1,%2,%3}, {%4,%5,%6,%7}, {%8,%9}, {%0,%1,%2,%3};"
        : "+f"(d[0]), "+f"(d[1]), "+f"(d[2]), "+f"(d[3])
        : "r"(a[0]), "r"(a[1]), "r"(a[2]), "r"(a[3]), "r"(b[0]), "r"(b[1]));
}
__device__ __forceinline__ float sigf(float x)   { return 1.0f / (1.0f + __expf(-x)); }
__device__ __forceinline__ float tanhf_(float x) { return 1.0f - 2.0f / (__expf(2.0f * x) + 1.0f); }

// ---------------------------------------------------------------------------
// persistent device state
// ---------------------------------------------------------------------------
__device__ float g_Hbuf0[HD * NB];   // h state, h-major [H][N] (tf32-rounded)
__device__ float g_Hbuf1[HD * NB];
__device__ float g_Cbuf [HD * NB];   // c state, h-major
__device__ float g_W1[NG * 256];     // permuted [4h+g][h|x]  (h cols first!)
__device__ float g_W2[NG * 128];     // permuted (W_ih+W_hh), tf32-rounded
__device__ float g_bias[NG];         // permuted b_ih + b_hh

// ---------------------------------------------------------------------------
// prep: row perm r = 4*h+g <- g*128+h. W1 column order: k<128 -> W_hh cols
// (h part FIRST), k>=128 -> W_ih cols (img). RNA-round; zero state.
// ---------------------------------------------------------------------------
__global__ void prep_kernel(const float* __restrict__ Wih, const float* __restrict__ Whh,
                            const float* __restrict__ bih, const float* __restrict__ bhh) {
    int tid = blockIdx.x * 256 + threadIdx.x;       // 512*256 = 131072
    int r = tid >> 8, k = tid & 255;
    int h = r >> 2, g = r & 3;
    int orig = g * HD + h;
    float v = (k < 128) ? Whh[orig * HD + k] : Wih[orig * HD + (k - 128)];
    g_W1[r * 256 + k] = __uint_as_float(rna_tf32(v));
    if (k < 128)
        g_W2[r * 128 + k] =
            __uint_as_float(rna_tf32(Wih[orig * HD + k] + Whh[orig * HD + k]));
    if (k == 0) g_bias[r] = bih[orig] + bhh[orig];
    for (int i = tid; i < HD * NB; i += 131072) {
        g_Hbuf0[i] = 0.0f;
        g_Cbuf[i]  = 0.0f;
    }
}

// ---------------------------------------------------------------------------
// smem layout (float offsets): bias(64) | 4x A(32x136) | 4x B(64x36)
// H2 stage (16 x 130) aliases A buffer 0 after the mainloop.
// ---------------------------------------------------------------------------
static constexpr int A_STR = 136, B_STR = 36, H_STR = 130;
static constexpr int A_FL  = 32 * A_STR;      // 4352
static constexpr int B_FL  = 64 * B_STR;      // 2304
static constexpr int OFF_BIAS = 0;
static constexpr int OFF_A    = 64;
static constexpr int OFF_B    = OFF_A + 4 * A_FL;
static constexpr int SM_FLOATS = OFF_B + 4 * B_FL;   // 26688
static constexpr int SM_BYTES  = SM_FLOATS * 4;      // 106752 -> 2 CTAs/SM

// ---------------------------------------------------------------------------
// fused step. CTA tile M=128 x N=64 (16 hidden units), K = NCH*32.
// Phase 1 (NCH=8): chunks 0-3 = h (W_hh cols), chunks 4-7 = img (W_ih cols).
// ---------------------------------------------------------------------------
template <int NCH>
__global__ void __launch_bounds__(256, 2)
lstm_step(const float* __restrict__ xsrc,   // [128][NB] x_t slice or null
          const float* __restrict__ hprev,  // [128][NB] (pre-rounded tf32)
          float* __restrict__ hnext,
          float* __restrict__ out, int t_out, int TOUT) {
    extern __shared__ float smf[];
    const uint32_t sb = smem_u32(smf);
    const int tid = threadIdx.x, lane = tid & 31, wid = tid >> 5;
    const int gq = lane >> 2, tig = lane & 3;
    const int wm = wid >> 1, wn = wid & 1;            // 4 x 2 warp grid
    const int j = blockIdx.x, n0 = blockIdx.y * 128;  // j: 64 gate cols

    if (tid < 64) smf[OFF_BIAS + tid] = g_bias[j * 64 + tid];

    const float* W = (NCH == 8) ? g_W1 : g_W2;
    const int KT = NCH * 32;

    auto loadC = [&](int ch) {
        const int buf = ch & 3;
        // h chunks first (warm L2), img chunks last (cold DRAM, deep prefetch)
        const float* asrc = (NCH == 8 && ch >= 4) ? xsrc : hprev;
        const int kr = (NCH == 8 && ch >= 4) ? (ch - 4) * 32 : ch * 32;
        const uint32_t ab = sb + (uint32_t)(OFF_A + buf * A_FL) * 4;
        const uint32_t bb = sb + (uint32_t)(OFF_B + buf * B_FL) * 4;
        #pragma unroll
        for (int it = 0; it < 4; it++) {   // A: 32 k-rows x 128 m
            int idx = tid + it * 256;
            int kk = idx >> 5, mp = (idx & 31) << 2;
            cp16(ab + (uint32_t)(kk * A_STR + mp) * 4,
                 asrc + (size_t)(kr + kk) * NB + n0 + mp);
        }
        #pragma unroll
        for (int it = 0; it < 2; it++) {   // B: 64 gate-cols x 32 k
            int idx = tid + it * 256;
            int n = idx >> 3, q = (idx & 7) << 2;
            cp16(bb + (uint32_t)(n * B_STR + q) * 4,
                 W + (size_t)(j * 64 + n) * KT + ch * 32 + q);
        }
        CP_COMMIT();
    };

    float acc[2][4][4];
    #pragma unroll
    for (int a0 = 0; a0 < 2; a0++)
        #pragma unroll
        for (int a1 = 0; a1 < 4; a1++)
            #pragma unroll
            for (int a2 = 0; a2 < 4; a2++) acc[a0][a1][a2] = 0.0f;

    loadC(0);
    loadC(1);
    loadC(2);
    #pragma unroll
    for (int ch = 0; ch < NCH; ch++) {
        // committed groups beyond ch: min(NCH-1, ch+2) - ch
        const int rem = NCH - 1 - ch;
        if (rem >= 2)      { CP_WAIT(2); }
        else if (rem == 1) { CP_WAIT(1); }
        else               { CP_WAIT(0); }
        __syncthreads();                   // chunk ch ready; mma(ch-1) done
        if (ch + 3 < NCH) loadC(ch + 3);   // writes buf (ch+3)&3 — free
        const float* As = smf + OFF_A + (ch & 3) * A_FL;
        const float* Bs = smf + OFF_B + (ch & 3) * B_FL;
        const bool docvt = (NCH == 8 && ch >= 4);   // img chunks need rounding

        #pragma unroll
        for (int kc = 0; kc < 4; kc++) {
            const int k0 = kc * 8;
            uint32_t a[2][4];
            #pragma unroll
            for (int mt = 0; mt < 2; mt++) {
                const int r0 = wm * 32 + mt * 16 + gq;
                float v0 = As[(k0 + tig) * A_STR + r0];
                float v1 = As[(k0 + tig) * A_STR + r0 + 8];
                float v2 = As[(k0 + tig + 4) * A_STR + r0];
                float v3 = As[(k0 + tig + 4) * A_STR + r0 + 8];
                if (docvt) {
                    a[mt][0] = rna_tf32(v0); a[mt][1] = rna_tf32(v1);
                    a[mt][2] = rna_tf32(v2); a[mt][3] = rna_tf32(v3);
                } else {
                    a[mt][0] = __float_as_uint(v0); a[mt][1] = __float_as_uint(v1);
                    a[mt][2] = __float_as_uint(v2); a[mt][3] = __float_as_uint(v3);
                }
            }
            #pragma unroll
            for (int nt = 0; nt < 4; nt++) {
                const int c0 = wn * 32 + nt * 8 + gq;
                uint32_t b[2];
                b[0] = __float_as_uint(Bs[c0 * B_STR + k0 + tig]);
                b[1] = __float_as_uint(Bs[c0 * B_STR + k0 + tig + 4]);
                mma8(acc[0][nt], a[0], b);
                mma8(acc[1][nt], a[1], b);
            }
        }
    }
    __syncthreads();     // all mma done -> A bufs reusable as H2 stage

    // ---- shuffle epilogue: pair (i,f) with (g,o) via lane^1 ----
    float* H2 = smf + OFF_A;            // 16 units x H_STR
    const int mymt = tig & 1;
    const int r0e = wm * 32 + mymt * 16 + gq;
    #pragma unroll
    for (int nt = 0; nt < 4; nt++) {
        const int u = wn * 8 + nt * 2 + (tig >> 1);
        float oth[4];
        #pragma unroll
        for (int e = 0; e < 4; e++)
            oth[e] = __shfl_xor_sync(0xffffffffu, acc[mymt ^ 1][nt][e], 1);
        const float b0 = smf[OFF_BIAS + 4 * u + 0];
        const float b1 = smf[OFF_BIAS + 4 * u + 1];
        const float b2 = smf[OFF_BIAS + 4 * u + 2];
        const float b3 = smf[OFF_BIAS + 4 * u + 3];
        #pragma unroll
        for (int e2 = 0; e2 < 2; e2++) {
            const float ow0 = acc[mymt][nt][2 * e2], ow1 = acc[mymt][nt][2 * e2 + 1];
            const float ot0 = oth[2 * e2],           ot1 = oth[2 * e2 + 1];
            float gi, gf, gg, go;
            if (mymt == 0) { gi = ow0; gf = ow1; gg = ot0; go = ot1; }
            else           { gg = ow0; go = ow1; gi = ot0; gf = ot1; }
            gi += b0; gf += b1; gg += b2; go += b3;
            const int row = r0e + 8 * e2;
            const size_t ci = (size_t)(j * 16 + u) * NB + n0 + row;
            const float cold = g_Cbuf[ci];
            const float cn = sigf(gf) * cold + sigf(gi) * tanhf_(gg);
            g_Cbuf[ci] = cn;
            H2[u * H_STR + row] = sigf(go) * tanhf_(cn);
        }
    }
    __syncthreads();

    // ---- h-state writeback (h-major, pre-rounded to tf32) ----
    #pragma unroll
    for (int q = 0; q < 2; q++) {
        const int u = wid * 2 + q;
        #pragma unroll
        for (int mk = 0; mk < 4; mk++) {
            const int m = mk * 32 + lane;
            hnext[(size_t)(j * 16 + u) * NB + n0 + m] =
                __uint_as_float(rna_tf32(H2[u * H_STR + m]));
        }
    }
    // ---- output: out[n][t][h], 64B contiguous (16 h per CTA) ----
    const int hh = lane & 15, rp = lane >> 4;
    #pragma unroll
    for (int i2 = 0; i2 < 8; i2++) {
        const int mr = wid * 16 + i2 * 2 + rp;
        out[(size_t)(n0 + mr) * TOUT * HD + (size_t)t_out * HD + j * 16 + hh] =
            H2[hh * H_STR + mr];
    }
}

// ---------------------------------------------------------------------------
// launch: prep + 60 K=256 steps + 54 K=128 steps
// ---------------------------------------------------------------------------
extern "C" void kernel_launch(void* const* d_in, const int* in_sizes, int n_in,
                              void* d_out, int out_size) {
    const float* img = (const float*)d_in[0];
    const float* Wih = (const float*)d_in[2];
    const float* Whh = (const float*)d_in[3];
    const float* bih = (const float*)d_in[4];
    const float* bhh = (const float*)d_in[5];
    float* out = (float*)d_out;

    const int T    = in_sizes[0] / (HD * NB);       // 60
    const int TOUT = out_size / (NB * HD);          // 114

    void *h0p, *h1p;
    cudaGetSymbolAddress(&h0p, g_Hbuf0);
    cudaGetSymbolAddress(&h1p, g_Hbuf1);
    float* hb[2] = {(float*)h0p, (float*)h1p};

    cudaFuncSetAttribute((const void*)lstm_step<8>,
                         cudaFuncAttributeMaxDynamicSharedMemorySize, SM_BYTES);
    cudaFuncSetAttribute((const void*)lstm_step<4>,
                         cudaFuncAttributeMaxDynamicSharedMemorySize, SM_BYTES);

    prep_kernel<<<512, 256>>>(Wih, Whh, bih, bhh);

    dim3 grid(8, NB / 128);                         // 256 CTAs, 2/SM
    for (int t = 0; t < TOUT; t++) {
        float* hp = hb[t & 1];
        float* hn = hb[(t + 1) & 1];
        if (t < T) {
            lstm_step<8><<<grid, 256, SM_BYTES>>>(
                img + (size_t)t * HD * NB, hp, hn, out, t, TOUT);
        } else {
            lstm_step<4><<<grid, 256, SM_BYTES>>>(
                nullptr, hp, hn, out, t, TOUT);
        }
    }
}